// round 12
// baseline (speedup 1.0000x reference)
#include <cuda_runtime.h>
#include <cstdint>
#include <cstddef>

// ---------------------------------------------------------------------------
// GCN 5-layer forward, max-aggregation (GB300).
//  [R11 preprocessing/gemm + NEW warp-per-node aggregation]
//  Aggregation: one warp per node, lane = feature. Indices fetched by ALL
//  lanes from the SAME int4 address (1 line -> 1 wavefront per 4 edges,
//  free in-register broadcast). Each gather LDG touches exactly ONE 128B
//  line -> 1.0 cyc/wf cross-LDG rate instead of 2.07 replay rate.
//  NO per-edge SHFL (measured poison). Next-layer GEMM fused via per-node
//  shfl matvec.
// ---------------------------------------------------------------------------

#define MAXN 200000
#define MAXE 7000000
#define MAXCHUNK 64
#define FULLM 0xffffffffu

__device__ int   g_cnt[MAXN];
__device__ int   g_cur[MAXN];
__device__ float g_dinv[MAXN];
__device__ int   g_off[MAXN + 1];
__device__ int   g_csr[MAXE];
__device__ int   g_bsums[MAXCHUNK];
__device__ float g_bufA[(size_t)MAXN * 32];
__device__ float g_bufB[(size_t)MAXN * 16];

__device__ __forceinline__ float fast_tanh(float x) {
    float y;
    asm("tanh.approx.f32 %0, %1;" : "=f"(y) : "f"(x));
    return y;
}

// ---------------- preprocessing ----------------

__global__ void k_count_v4(const int* __restrict__ col, int e4) {
    int i = blockIdx.x * blockDim.x + threadIdx.x;
    if (i < e4) {
        int4 c = reinterpret_cast<const int4*>(col)[i];
        atomicAdd(&g_cnt[c.x], 1);
        atomicAdd(&g_cnt[c.y], 1);
        atomicAdd(&g_cnt[c.z], 1);
        atomicAdd(&g_cnt[c.w], 1);
    }
}

__global__ void k_count(const int* __restrict__ col, int e) {
    int i = blockIdx.x * blockDim.x + threadIdx.x;
    if (i < e) atomicAdd(&g_cnt[col[i]], 1);
}

// chunk sums of PADDED counts + dinv from true counts
__global__ void k_scan1(int n) {
    int i = blockIdx.x * blockDim.x + threadIdx.x;
    int vp = 0;
    if (i < n) {
        int v = g_cnt[i];
        g_dinv[i] = rsqrtf((float)v + 1.0f);
        vp = (v + 3) & ~3;
    }
    #pragma unroll
    for (int o = 16; o; o >>= 1) vp += __shfl_down_sync(FULLM, vp, o);
    if ((threadIdx.x & 31) == 0) atomicAdd(&g_bsums[blockIdx.x >> 2], vp);
}

__global__ void k_scan3(int n, int nchunks) {
    __shared__ int wsum[32];
    __shared__ int s_base;
    if (threadIdx.x < 32) {
        int l = threadIdx.x;
        int a = (l < nchunks) ? g_bsums[l] : 0;
        int b = (l + 32 < nchunks) ? g_bsums[l + 32] : 0;
        int pre = ((l < (int)blockIdx.x) ? a : 0) + ((l + 32 < (int)blockIdx.x) ? b : 0);
        int tot = a + b;
        #pragma unroll
        for (int o = 16; o; o >>= 1) {
            pre += __shfl_down_sync(FULLM, pre, o);
            tot += __shfl_down_sync(FULLM, tot, o);
        }
        if (l == 0) {
            s_base = pre;
            if (blockIdx.x == gridDim.x - 1) g_off[n] = tot;
        }
    }
    int base = blockIdx.x * 4096 + threadIdx.x * 4;
    int v[4]; int s = 0;
    #pragma unroll
    for (int j = 0; j < 4; j++) {
        int idx = base + j;
        v[j] = (idx < n) ? ((g_cnt[idx] + 3) & ~3) : 0;
        s += v[j];
    }
    int lane = threadIdx.x & 31, w = threadIdx.x >> 5;
    int inc = s;
    #pragma unroll
    for (int o = 1; o < 32; o <<= 1) { int t = __shfl_up_sync(FULLM, inc, o); if (lane >= o) inc += t; }
    if (lane == 31) wsum[w] = inc;
    __syncthreads();
    if (w == 0) {
        int ws = wsum[lane];
        #pragma unroll
        for (int o = 1; o < 32; o <<= 1) { int t = __shfl_up_sync(FULLM, ws, o); if (lane >= o) ws += t; }
        wsum[lane] = ws;
    }
    __syncthreads();
    int ex = inc - s + (w ? wsum[w - 1] : 0) + s_base;
    #pragma unroll
    for (int j = 0; j < 4; j++) { int idx = base + j; if (idx < n) g_off[idx] = ex; ex += v[j]; }
}

__global__ void k_fill_v4(const int* __restrict__ row, const int* __restrict__ col, int e4) {
    int i = blockIdx.x * blockDim.x + threadIdx.x;
    if (i >= e4) return;
    int4 r = reinterpret_cast<const int4*>(row)[i];
    int4 c = reinterpret_cast<const int4*>(col)[i];
    int p0 = g_off[c.x] + atomicAdd(&g_cur[c.x], 1); g_csr[p0] = r.x;
    int p1 = g_off[c.y] + atomicAdd(&g_cur[c.y], 1); g_csr[p1] = r.y;
    int p2 = g_off[c.z] + atomicAdd(&g_cur[c.z], 1); g_csr[p2] = r.z;
    int p3 = g_off[c.w] + atomicAdd(&g_cur[c.w], 1); g_csr[p3] = r.w;
}

__global__ void k_fill(const int* __restrict__ row, const int* __restrict__ col, int e) {
    int i = blockIdx.x * blockDim.x + threadIdx.x;
    if (i >= e) return;
    int c = col[i];
    int p = g_off[c] + atomicAdd(&g_cur[c], 1);
    g_csr[p] = row[i];
}

__global__ void k_pad(int n) {
    int i = blockIdx.x * blockDim.x + threadIdx.x;
    if (i >= n) return;
    int c = g_cnt[i];
    int pc = (c + 3) & ~3;
    int off = g_off[i];
    for (int j = c; j < pc; j++) g_csr[off + j] = i;
}

// ---------------- layer 1 GEMM (raw):  xl = x @ W1, packed f32x2 ------------

__device__ __forceinline__ unsigned long long pk2(float x, float y) {
    unsigned long long r;
    asm("mov.b64 %0, {%1, %2};" : "=l"(r) : "f"(x), "f"(y));
    return r;
}
__device__ __forceinline__ void upk2(unsigned long long v, float& x, float& y) {
    asm("mov.b64 {%0, %1}, %2;" : "=f"(x), "=f"(y) : "l"(v));
}
__device__ __forceinline__ void ffma2(unsigned long long& acc, unsigned long long a,
                                      unsigned long long b) {
    asm("fma.rn.f32x2 %0, %1, %2, %3;" : "=l"(acc) : "l"(a), "l"(b), "l"(acc));
}

__global__ void __launch_bounds__(256) k_gemm1_raw(const float* __restrict__ x,
                                                   const float* __restrict__ W, int n) {
    __shared__ unsigned long long Ws[128 * 12];
    const unsigned long long* Wp = reinterpret_cast<const unsigned long long*>(W);
    for (int i = threadIdx.x; i < 128 * 12; i += blockDim.x) Ws[i] = Wp[i];
    __syncthreads();
    int r = blockIdx.x * blockDim.x + threadIdx.x;
    if (r >= n) return;
    const float4* s4 = reinterpret_cast<const float4*>(x + (size_t)r * 128);
    unsigned long long acc[12];
    #pragma unroll
    for (int j = 0; j < 12; j++) acc[j] = 0ull;
    #pragma unroll 4
    for (int k4 = 0; k4 < 32; k4++) {
        float4 xv = s4[k4];
        unsigned long long a0 = pk2(xv.x, xv.x);
        unsigned long long a1 = pk2(xv.y, xv.y);
        unsigned long long a2 = pk2(xv.z, xv.z);
        unsigned long long a3 = pk2(xv.w, xv.w);
        #pragma unroll
        for (int j = 0; j < 12; j++) {
            ffma2(acc[j], a0, Ws[(4 * k4 + 0) * 12 + j]);
            ffma2(acc[j], a1, Ws[(4 * k4 + 1) * 12 + j]);
            ffma2(acc[j], a2, Ws[(4 * k4 + 2) * 12 + j]);
            ffma2(acc[j], a3, Ws[(4 * k4 + 3) * 12 + j]);
        }
    }
    #pragma unroll
    for (int j = 0; j < 12; j++) {
        float a, b;
        upk2(acc[j], a, b);
        g_bufA[(size_t)r * 32 + 2 * j]     = a;
        g_bufA[(size_t)r * 32 + 2 * j + 1] = b;
    }
}

__global__ void __launch_bounds__(256) k_scale(int n) {
    int r = blockIdx.x * blockDim.x + threadIdx.x;
    if (r >= n) return;
    float dv = g_dinv[r];
    float4* p = reinterpret_cast<float4*>(g_bufA + (size_t)r * 32);
    #pragma unroll
    for (int j = 0; j < 6; j++) {
        float4 v = p[j];
        v.x *= dv; v.y *= dv; v.z *= dv; v.w *= dv;
        p[j] = v;
    }
}

// ---------------- warp-per-node aggregation + fused next GEMM ---------------
// Lane = feature (lane < D active). Indices: all lanes load the SAME int4
// (1 line, free broadcast). Each gather LDG = one row = one 128B line.
// Segments 4-aligned & 4-padded: no peel/tail.

template <int D, int PIN, int DOUT, int POUT>
__global__ void __launch_bounds__(256) k_aggw(const float* __restrict__ yin,
                                              float* __restrict__ yout,
                                              const float* __restrict__ bias,
                                              const float* __restrict__ Wn, int n) {
    __shared__ float Ws[D * DOUT];
    for (int i = threadIdx.x; i < D * DOUT; i += blockDim.x) Ws[i] = Wn[i];
    __syncthreads();
    int node = (blockIdx.x * blockDim.x + threadIdx.x) >> 5;
    if (node >= n) return;
    int lane = threadIdx.x & 31;
    bool act = lane < D;

    int s = g_off[node], e = g_off[node + 1];
    float m = act ? yin[(size_t)node * PIN + lane] : 0.f;   // self loop

    int i = s;
    for (; i + 8 <= e; i += 8) {
        // warp-uniform index loads: every lane reads the same int4 (1 line)
        int4 ia = *reinterpret_cast<const int4*>(g_csr + i);
        int4 ib = *reinterpret_cast<const int4*>(g_csr + i + 4);
        if (act) {
            float v0 = yin[(size_t)ia.x * PIN + lane];
            float v1 = yin[(size_t)ia.y * PIN + lane];
            float v2 = yin[(size_t)ia.z * PIN + lane];
            float v3 = yin[(size_t)ia.w * PIN + lane];
            float v4 = yin[(size_t)ib.x * PIN + lane];
            float v5 = yin[(size_t)ib.y * PIN + lane];
            float v6 = yin[(size_t)ib.z * PIN + lane];
            float v7 = yin[(size_t)ib.w * PIN + lane];
            m = fmaxf(m, fmaxf(fmaxf(v0, v1), fmaxf(v2, v3)));
            m = fmaxf(m, fmaxf(fmaxf(v4, v5), fmaxf(v6, v7)));
        }
    }
    if (i < e) {   // exactly one int4 remains
        int4 ia = *reinterpret_cast<const int4*>(g_csr + i);
        if (act) {
            float v0 = yin[(size_t)ia.x * PIN + lane];
            float v1 = yin[(size_t)ia.y * PIN + lane];
            float v2 = yin[(size_t)ia.z * PIN + lane];
            float v3 = yin[(size_t)ia.w * PIN + lane];
            m = fmaxf(m, fmaxf(fmaxf(v0, v1), fmaxf(v2, v3)));
        }
    }

    float dv = g_dinv[node];
    float h = fast_tanh(dv * m + (act ? bias[lane] : 0.f));

    // per-node matvec: D shfls + D FMAs (NOT per-edge)
    float acc = 0.f;
    #pragma unroll
    for (int k = 0; k < D; k++) {
        float hk = __shfl_sync(FULLM, h, k);
        if (lane < DOUT) acc += hk * Ws[k * DOUT + lane];
    }
    if (lane < DOUT) yout[(size_t)node * POUT + lane] = dv * acc;
}

// Final layer: D=2, warp per node, classifier epilogue.
__global__ void __launch_bounds__(256) k_agg_fin(const float* __restrict__ yin,
                                                 const float* __restrict__ bias,
                                                 const float* __restrict__ Wc,
                                                 const float* __restrict__ bc,
                                                 float* __restrict__ out, int n, int write_h) {
    int node = (blockIdx.x * blockDim.x + threadIdx.x) >> 5;
    if (node >= n) return;
    int lane = threadIdx.x & 31;
    bool act = lane < 2;

    int s = g_off[node], e = g_off[node + 1];
    float m = act ? yin[(size_t)node * 2 + lane] : 0.f;

    int i = s;
    for (; i + 8 <= e; i += 8) {
        int4 ia = *reinterpret_cast<const int4*>(g_csr + i);
        int4 ib = *reinterpret_cast<const int4*>(g_csr + i + 4);
        if (act) {
            float v0 = yin[(size_t)ia.x * 2 + lane];
            float v1 = yin[(size_t)ia.y * 2 + lane];
            float v2 = yin[(size_t)ia.z * 2 + lane];
            float v3 = yin[(size_t)ia.w * 2 + lane];
            float v4 = yin[(size_t)ib.x * 2 + lane];
            float v5 = yin[(size_t)ib.y * 2 + lane];
            float v6 = yin[(size_t)ib.z * 2 + lane];
            float v7 = yin[(size_t)ib.w * 2 + lane];
            m = fmaxf(m, fmaxf(fmaxf(v0, v1), fmaxf(v2, v3)));
            m = fmaxf(m, fmaxf(fmaxf(v4, v5), fmaxf(v6, v7)));
        }
    }
    if (i < e) {
        int4 ia = *reinterpret_cast<const int4*>(g_csr + i);
        if (act) {
            float v0 = yin[(size_t)ia.x * 2 + lane];
            float v1 = yin[(size_t)ia.y * 2 + lane];
            float v2 = yin[(size_t)ia.z * 2 + lane];
            float v3 = yin[(size_t)ia.w * 2 + lane];
            m = fmaxf(m, fmaxf(fmaxf(v0, v1), fmaxf(v2, v3)));
        }
    }

    float dv = g_dinv[node];
    float h = fast_tanh(dv * m + (act ? bias[lane] : 0.f));
    float h0 = __shfl_sync(FULLM, h, 0);
    float h1 = __shfl_sync(FULLM, h, 1);
    if (lane < 4)
        out[(size_t)node * 4 + lane] = h0 * Wc[lane] + h1 * Wc[4 + lane] + bc[lane];
    if (write_h && lane >= 4 && lane < 6)
        out[(size_t)4 * n + (size_t)node * 2 + (lane - 4)] = (lane == 4) ? h0 : h1;
}

// ---------------- launch ----------------

extern "C" void kernel_launch(void* const* d_in, const int* in_sizes, int n_in,
                              void* d_out, int out_size) {
    const float* x  = (const float*)d_in[0];
    const int*   ei = (const int*)d_in[1];
    const float* W1 = (const float*)d_in[2];  const float* b1 = (const float*)d_in[3];
    const float* W2 = (const float*)d_in[4];  const float* b2 = (const float*)d_in[5];
    const float* W3 = (const float*)d_in[6];  const float* b3 = (const float*)d_in[7];
    const float* W4 = (const float*)d_in[8];  const float* b4 = (const float*)d_in[9];
    const float* W5 = (const float*)d_in[10]; const float* b5 = (const float*)d_in[11];
    const float* Wc = (const float*)d_in[12]; const float* bc = (const float*)d_in[13];

    int n = in_sizes[0] / 128;
    int e = in_sizes[1] / 2;
    const int* row = ei;
    const int* col = ei + e;

    const int TB = 256;
    int nchunks = (n + 4095) / 4096;
    int nwblk = (n + 7) / 8;   // 8 warps/block, warp per node

    float* bufA = nullptr; float* bufB = nullptr;
    int *cntp = nullptr, *curp = nullptr, *bsump = nullptr;
    cudaGetSymbolAddress((void**)&bufA, g_bufA);
    cudaGetSymbolAddress((void**)&bufB, g_bufB);
    cudaGetSymbolAddress((void**)&cntp, g_cnt);
    cudaGetSymbolAddress((void**)&curp, g_cur);
    cudaGetSymbolAddress((void**)&bsump, g_bsums);

    static cudaStream_t s2 = nullptr;
    static cudaEvent_t evFork = nullptr, evScan1 = nullptr, evScan3 = nullptr, evJoin = nullptr;
    if (s2 == nullptr) {
        cudaStreamCreateWithFlags(&s2, cudaStreamNonBlocking);
        cudaEventCreateWithFlags(&evFork,  cudaEventDisableTiming);
        cudaEventCreateWithFlags(&evScan1, cudaEventDisableTiming);
        cudaEventCreateWithFlags(&evScan3, cudaEventDisableTiming);
        cudaEventCreateWithFlags(&evJoin,  cudaEventDisableTiming);
    }

    bool vec_ok = ((e & 3) == 0) &&
                  (((size_t)col & 15) == 0) &&
                  (((size_t)row & 15) == 0);

    // fork: gemm1_raw independent of CSR build
    cudaEventRecord(evFork, 0);
    cudaStreamWaitEvent(s2, evFork, 0);
    k_gemm1_raw<<<(n + TB - 1) / TB, TB, 0, s2>>>(x, W1, n);   // -> bufA raw

    // default stream: CSR build
    cudaMemsetAsync(cntp, 0, (size_t)n * 4, 0);
    cudaMemsetAsync(curp, 0, (size_t)n * 4, 0);
    cudaMemsetAsync(bsump, 0, (size_t)MAXCHUNK * 4, 0);
    if (vec_ok) k_count_v4<<<(e / 4 + TB - 1) / TB, TB>>>(col, e / 4);
    else        k_count   <<<(e + TB - 1) / TB, TB>>>(col, e);
    k_scan1<<<(n + 1023) / 1024, 1024>>>(n);
    cudaEventRecord(evScan1, 0);
    k_scan3<<<nchunks, 1024>>>(n, nchunks);
    cudaEventRecord(evScan3, 0);
    if (vec_ok) k_fill_v4<<<(e / 4 + TB - 1) / TB, TB>>>(row, col, e / 4);
    else        k_fill   <<<(e + TB - 1) / TB, TB>>>(row, col, e);

    // s2: scale (after scan1), pad (after scan3; disjoint from fill's region)
    cudaStreamWaitEvent(s2, evScan1, 0);
    k_scale<<<(n + TB - 1) / TB, TB, 0, s2>>>(n);
    cudaStreamWaitEvent(s2, evScan3, 0);
    k_pad<<<(n + TB - 1) / TB, TB, 0, s2>>>(n);
    cudaEventRecord(evJoin, s2);
    cudaStreamWaitEvent(0, evJoin, 0);

    // <D, PIN, DOUT, POUT>
    k_aggw<24, 32, 12, 16><<<nwblk, TB>>>(bufA, bufB, b1, W2, n);
    k_aggw<12, 16,  6,  8><<<nwblk, TB>>>(bufB, bufA, b2, W3, n);
    k_aggw< 6,  8,  4,  4><<<nwblk, TB>>>(bufA, bufB, b3, W4, n);
    k_aggw< 4,  4,  2,  2><<<nwblk, TB>>>(bufB, bufA, b4, W5, n);

    int write_h = (out_size >= 6 * n) ? 1 : 0;
    k_agg_fin<<<nwblk, TB>>>(bufA, b5, Wc, bc, (float*)d_out, n, write_h);
}

// round 13
// speedup vs baseline: 1.5661x; 1.5661x over previous
#include <cuda_runtime.h>
#include <cstdint>
#include <cstddef>

// ---------------------------------------------------------------------------
// GCN 5-layer forward, max-aggregation (GB300).
//  [R11 structure — best known — with CSR-build trims]
//  - scan3 writes offsets AND pad entries (k_pad kernel removed)
//  - k_fill bumps a working-offset copy directly (g_cur + per-edge off load gone)
//  Streams: s2: gemm1_raw → wait(scan1) → scale ; s0: CSR build → aggs
// ---------------------------------------------------------------------------

#define MAXN 200000
#define MAXE 7000000
#define MAXCHUNK 64
#define FULLM 0xffffffffu

__device__ int   g_cnt[MAXN];
__device__ float g_dinv[MAXN];
__device__ int   g_off[MAXN + 1];
__device__ int   g_woff[MAXN];     // mutable copy for fill
__device__ int   g_csr[MAXE];
__device__ int   g_bsums[MAXCHUNK];
__device__ float g_bufA[(size_t)MAXN * 32];
__device__ float g_bufB[(size_t)MAXN * 16];

__device__ __forceinline__ float fast_tanh(float x) {
    float y;
    asm("tanh.approx.f32 %0, %1;" : "=f"(y) : "f"(x));
    return y;
}

template <int V> __device__ __forceinline__ void vld(float* d, const float* p);
template <> __device__ __forceinline__ void vld<4>(float* d, const float* p) {
    float4 t = *reinterpret_cast<const float4*>(p);
    d[0] = t.x; d[1] = t.y; d[2] = t.z; d[3] = t.w;
}
template <> __device__ __forceinline__ void vld<2>(float* d, const float* p) {
    float2 t = *reinterpret_cast<const float2*>(p);
    d[0] = t.x; d[1] = t.y;
}
template <int V> __device__ __forceinline__ void vst(float* p, const float* d);
template <> __device__ __forceinline__ void vst<4>(float* p, const float* d) {
    *reinterpret_cast<float4*>(p) = make_float4(d[0], d[1], d[2], d[3]);
}
template <> __device__ __forceinline__ void vst<2>(float* p, const float* d) {
    *reinterpret_cast<float2*>(p) = make_float2(d[0], d[1]);
}

template <int V>
__device__ __forceinline__ void vmax(float* m, const float* a) {
    #pragma unroll
    for (int c = 0; c < V; c++) m[c] = fmaxf(m[c], a[c]);
}

// ---------------- preprocessing ----------------

__global__ void k_count_v4(const int* __restrict__ col, int e4) {
    int i = blockIdx.x * blockDim.x + threadIdx.x;
    if (i < e4) {
        int4 c = reinterpret_cast<const int4*>(col)[i];
        atomicAdd(&g_cnt[c.x], 1);
        atomicAdd(&g_cnt[c.y], 1);
        atomicAdd(&g_cnt[c.z], 1);
        atomicAdd(&g_cnt[c.w], 1);
    }
}

__global__ void k_count(const int* __restrict__ col, int e) {
    int i = blockIdx.x * blockDim.x + threadIdx.x;
    if (i < e) atomicAdd(&g_cnt[col[i]], 1);
}

// chunk sums of PADDED counts + dinv from true counts
__global__ void k_scan1(int n) {
    int i = blockIdx.x * blockDim.x + threadIdx.x;
    int vp = 0;
    if (i < n) {
        int v = g_cnt[i];
        g_dinv[i] = rsqrtf((float)v + 1.0f);
        vp = (v + 3) & ~3;
    }
    #pragma unroll
    for (int o = 16; o; o >>= 1) vp += __shfl_down_sync(FULLM, vp, o);
    if ((threadIdx.x & 31) == 0) atomicAdd(&g_bsums[blockIdx.x >> 2], vp);
}

// per-chunk exclusive scan of padded counts; ALSO writes pad entries + woff
__global__ void k_scan3(int n, int nchunks) {
    __shared__ int wsum[32];
    __shared__ int s_base;
    if (threadIdx.x < 32) {
        int l = threadIdx.x;
        int a = (l < nchunks) ? g_bsums[l] : 0;
        int b = (l + 32 < nchunks) ? g_bsums[l + 32] : 0;
        int pre = ((l < (int)blockIdx.x) ? a : 0) + ((l + 32 < (int)blockIdx.x) ? b : 0);
        int tot = a + b;
        #pragma unroll
        for (int o = 16; o; o >>= 1) {
            pre += __shfl_down_sync(FULLM, pre, o);
            tot += __shfl_down_sync(FULLM, tot, o);
        }
        if (l == 0) {
            s_base = pre;
            if (blockIdx.x == gridDim.x - 1) g_off[n] = tot;
        }
    }
    int base = blockIdx.x * 4096 + threadIdx.x * 4;
    int cnt[4], v[4]; int s = 0;
    #pragma unroll
    for (int j = 0; j < 4; j++) {
        int idx = base + j;
        cnt[j] = (idx < n) ? g_cnt[idx] : 0;
        v[j] = (cnt[j] + 3) & ~3;
        s += v[j];
    }
    int lane = threadIdx.x & 31, w = threadIdx.x >> 5;
    int inc = s;
    #pragma unroll
    for (int o = 1; o < 32; o <<= 1) { int t = __shfl_up_sync(FULLM, inc, o); if (lane >= o) inc += t; }
    if (lane == 31) wsum[w] = inc;
    __syncthreads();
    if (w == 0) {
        int ws = wsum[lane];
        #pragma unroll
        for (int o = 1; o < 32; o <<= 1) { int t = __shfl_up_sync(FULLM, ws, o); if (lane >= o) ws += t; }
        wsum[lane] = ws;
    }
    __syncthreads();
    int ex = inc - s + (w ? wsum[w - 1] : 0) + s_base;
    #pragma unroll
    for (int j = 0; j < 4; j++) {
        int idx = base + j;
        if (idx < n) {
            g_off[idx]  = ex;
            g_woff[idx] = ex;
            // pad slots [cnt, vpad) with own index (harmless under max)
            for (int k = cnt[j]; k < v[j]; k++) g_csr[ex + k] = idx;
        }
        ex += v[j];
    }
}

__global__ void k_fill_v4(const int* __restrict__ row, const int* __restrict__ col, int e4) {
    int i = blockIdx.x * blockDim.x + threadIdx.x;
    if (i >= e4) return;
    int4 r = reinterpret_cast<const int4*>(row)[i];
    int4 c = reinterpret_cast<const int4*>(col)[i];
    g_csr[atomicAdd(&g_woff[c.x], 1)] = r.x;
    g_csr[atomicAdd(&g_woff[c.y], 1)] = r.y;
    g_csr[atomicAdd(&g_woff[c.z], 1)] = r.z;
    g_csr[atomicAdd(&g_woff[c.w], 1)] = r.w;
}

__global__ void k_fill(const int* __restrict__ row, const int* __restrict__ col, int e) {
    int i = blockIdx.x * blockDim.x + threadIdx.x;
    if (i >= e) return;
    int c = col[i];
    g_csr[atomicAdd(&g_woff[c], 1)] = row[i];
}

// ---------------- layer 1 GEMM (raw):  xl = x @ W1, packed f32x2 ------------

__device__ __forceinline__ unsigned long long pk2(float x, float y) {
    unsigned long long r;
    asm("mov.b64 %0, {%1, %2};" : "=l"(r) : "f"(x), "f"(y));
    return r;
}
__device__ __forceinline__ void upk2(unsigned long long v, float& x, float& y) {
    asm("mov.b64 {%0, %1}, %2;" : "=f"(x), "=f"(y) : "l"(v));
}
__device__ __forceinline__ void ffma2(unsigned long long& acc, unsigned long long a,
                                      unsigned long long b) {
    asm("fma.rn.f32x2 %0, %1, %2, %3;" : "=l"(acc) : "l"(a), "l"(b), "l"(acc));
}

__global__ void __launch_bounds__(256) k_gemm1_raw(const float* __restrict__ x,
                                                   const float* __restrict__ W, int n) {
    __shared__ unsigned long long Ws[128 * 12];
    const unsigned long long* Wp = reinterpret_cast<const unsigned long long*>(W);
    for (int i = threadIdx.x; i < 128 * 12; i += blockDim.x) Ws[i] = Wp[i];
    __syncthreads();
    int r = blockIdx.x * blockDim.x + threadIdx.x;
    if (r >= n) return;
    const float4* s4 = reinterpret_cast<const float4*>(x + (size_t)r * 128);
    unsigned long long acc[12];
    #pragma unroll
    for (int j = 0; j < 12; j++) acc[j] = 0ull;
    #pragma unroll 4
    for (int k4 = 0; k4 < 32; k4++) {
        float4 xv = s4[k4];
        unsigned long long a0 = pk2(xv.x, xv.x);
        unsigned long long a1 = pk2(xv.y, xv.y);
        unsigned long long a2 = pk2(xv.z, xv.z);
        unsigned long long a3 = pk2(xv.w, xv.w);
        #pragma unroll
        for (int j = 0; j < 12; j++) {
            ffma2(acc[j], a0, Ws[(4 * k4 + 0) * 12 + j]);
            ffma2(acc[j], a1, Ws[(4 * k4 + 1) * 12 + j]);
            ffma2(acc[j], a2, Ws[(4 * k4 + 2) * 12 + j]);
            ffma2(acc[j], a3, Ws[(4 * k4 + 3) * 12 + j]);
        }
    }
    #pragma unroll
    for (int j = 0; j < 12; j++) {
        float a, b;
        upk2(acc[j], a, b);
        g_bufA[(size_t)r * 32 + 2 * j]     = a;
        g_bufA[(size_t)r * 32 + 2 * j + 1] = b;
    }
}

__global__ void __launch_bounds__(256) k_scale(int n) {
    int r = blockIdx.x * blockDim.x + threadIdx.x;
    if (r >= n) return;
    float dv = g_dinv[r];
    float4* p = reinterpret_cast<float4*>(g_bufA + (size_t)r * 32);
    #pragma unroll
    for (int j = 0; j < 6; j++) {
        float4 v = p[j];
        v.x *= dv; v.y *= dv; v.z *= dv; v.w *= dv;
        p[j] = v;
    }
}

// ---------------- fused aggregation + next-layer GEMM -----------------------
// G lanes per node; lane g owns features [g*V, g*V+V). Segments 4-aligned &
// 4-padded: pure int4 index loads, no peel/tail. (R11 structure, best known.)

template <int D, int V, int G, int PIN, int DOUT, int VOUT, int POUT>
__global__ void __launch_bounds__(256) k_aggv(const float* __restrict__ yin,
                                              float* __restrict__ yout,
                                              const float* __restrict__ bias,
                                              const float* __restrict__ Wn, int n) {
    constexpr int ACT = D / V;
    constexpr int OACT = DOUT / VOUT;
    __shared__ float Ws[D * DOUT];
    for (int i = threadIdx.x; i < D * DOUT; i += blockDim.x) Ws[i] = Wn[i];
    __syncthreads();
    int t = blockIdx.x * blockDim.x + threadIdx.x;
    int node = (G == 1) ? t : (t / G);
    int g = (G == 1) ? 0 : (t & (G - 1));
    bool valid = node < n;
    if (!valid) node = n - 1;
    bool active = (G == 1) || (g < ACT);
    int lane = threadIdx.x & 31;
    unsigned gmask = (G == 32) ? FULLM : (((1u << G) - 1u) << (lane & ~(G - 1)));

    int s = g_off[node], e = g_off[node + 1];
    float m[V];
    #pragma unroll
    for (int c = 0; c < V; c++) m[c] = 0.f;
    if (active) vld<V>(m, yin + (size_t)node * PIN + g * V);   // self loop

    int i = s;
    for (; i + 8 <= e; i += 8) {
        int4 ia = *reinterpret_cast<const int4*>(g_csr + i);
        int4 ib = *reinterpret_cast<const int4*>(g_csr + i + 4);
        if (active) {
            float a0[V], a1[V], a2[V], a3[V], a4[V], a5[V], a6[V], a7[V];
            vld<V>(a0, yin + (size_t)ia.x * PIN + g * V);
            vld<V>(a1, yin + (size_t)ia.y * PIN + g * V);
            vld<V>(a2, yin + (size_t)ia.z * PIN + g * V);
            vld<V>(a3, yin + (size_t)ia.w * PIN + g * V);
            vld<V>(a4, yin + (size_t)ib.x * PIN + g * V);
            vld<V>(a5, yin + (size_t)ib.y * PIN + g * V);
            vld<V>(a6, yin + (size_t)ib.z * PIN + g * V);
            vld<V>(a7, yin + (size_t)ib.w * PIN + g * V);
            vmax<V>(m, a0); vmax<V>(m, a1); vmax<V>(m, a2); vmax<V>(m, a3);
            vmax<V>(m, a4); vmax<V>(m, a5); vmax<V>(m, a6); vmax<V>(m, a7);
        }
    }
    if (i < e) {   // exactly one int4 remains (length % 4 == 0)
        int4 ia = *reinterpret_cast<const int4*>(g_csr + i);
        if (active) {
            float a0[V], a1[V], a2[V], a3[V];
            vld<V>(a0, yin + (size_t)ia.x * PIN + g * V);
            vld<V>(a1, yin + (size_t)ia.y * PIN + g * V);
            vld<V>(a2, yin + (size_t)ia.z * PIN + g * V);
            vld<V>(a3, yin + (size_t)ia.w * PIN + g * V);
            vmax<V>(m, a0); vmax<V>(m, a1); vmax<V>(m, a2); vmax<V>(m, a3);
        }
    }

    float dv = g_dinv[node];
    float h[V];
    #pragma unroll
    for (int c = 0; c < V; c++) {
        float bv = active ? bias[g * V + c] : 0.f;
        h[c] = fast_tanh(dv * m[c] + bv);
    }

    float acc[VOUT];
    #pragma unroll
    for (int v = 0; v < VOUT; v++) acc[v] = 0.f;

    if constexpr (G == 1) {
        #pragma unroll
        for (int k = 0; k < D; k++)
            #pragma unroll
            for (int v = 0; v < VOUT; v++) acc[v] += h[k] * Ws[k * DOUT + v];
    } else {
        #pragma unroll
        for (int src = 0; src < ACT; src++) {
            #pragma unroll
            for (int c = 0; c < V; c++) {
                float hk = __shfl_sync(gmask, h[c], src, G);   // once per NODE
                if (g < OACT) {
                    #pragma unroll
                    for (int v = 0; v < VOUT; v++)
                        acc[v] += hk * Ws[(src * V + c) * DOUT + g * VOUT + v];
                }
            }
        }
    }
    if (valid && ((G == 1) || g < OACT)) {
        float outv[VOUT];
        #pragma unroll
        for (int v = 0; v < VOUT; v++) outv[v] = dv * acc[v];
        vst<VOUT>(yout + (size_t)node * POUT + g * VOUT, outv);
    }
}

// Final layer: D=2, one lane per node, classifier epilogue.
__global__ void __launch_bounds__(256) k_agg_fin(const float* __restrict__ yin,
                                                 const float* __restrict__ bias,
                                                 const float* __restrict__ Wc,
                                                 const float* __restrict__ bc,
                                                 float* __restrict__ out, int n, int write_h) {
    int node = blockIdx.x * blockDim.x + threadIdx.x;
    if (node >= n) return;
    int s = g_off[node], e = g_off[node + 1];
    float2 m = *reinterpret_cast<const float2*>(yin + (size_t)node * 2);
    int i = s;
    for (; i + 8 <= e; i += 8) {
        int4 ia = *reinterpret_cast<const int4*>(g_csr + i);
        int4 ib = *reinterpret_cast<const int4*>(g_csr + i + 4);
        float2 a0 = *reinterpret_cast<const float2*>(yin + (size_t)ia.x * 2);
        float2 a1 = *reinterpret_cast<const float2*>(yin + (size_t)ia.y * 2);
        float2 a2 = *reinterpret_cast<const float2*>(yin + (size_t)ia.z * 2);
        float2 a3 = *reinterpret_cast<const float2*>(yin + (size_t)ia.w * 2);
        float2 a4 = *reinterpret_cast<const float2*>(yin + (size_t)ib.x * 2);
        float2 a5 = *reinterpret_cast<const float2*>(yin + (size_t)ib.y * 2);
        float2 a6 = *reinterpret_cast<const float2*>(yin + (size_t)ib.z * 2);
        float2 a7 = *reinterpret_cast<const float2*>(yin + (size_t)ib.w * 2);
        m.x = fmaxf(m.x, fmaxf(fmaxf(a0.x, a1.x), fmaxf(a2.x, a3.x)));
        m.x = fmaxf(m.x, fmaxf(fmaxf(a4.x, a5.x), fmaxf(a6.x, a7.x)));
        m.y = fmaxf(m.y, fmaxf(fmaxf(a0.y, a1.y), fmaxf(a2.y, a3.y)));
        m.y = fmaxf(m.y, fmaxf(fmaxf(a4.y, a5.y), fmaxf(a6.y, a7.y)));
    }
    if (i < e) {
        int4 ia = *reinterpret_cast<const int4*>(g_csr + i);
        float2 a0 = *reinterpret_cast<const float2*>(yin + (size_t)ia.x * 2);
        float2 a1 = *reinterpret_cast<const float2*>(yin + (size_t)ia.y * 2);
        float2 a2 = *reinterpret_cast<const float2*>(yin + (size_t)ia.z * 2);
        float2 a3 = *reinterpret_cast<const float2*>(yin + (size_t)ia.w * 2);
        m.x = fmaxf(m.x, fmaxf(fmaxf(a0.x, a1.x), fmaxf(a2.x, a3.x)));
        m.y = fmaxf(m.y, fmaxf(fmaxf(a0.y, a1.y), fmaxf(a2.y, a3.y)));
    }
    float dv = g_dinv[node];
    float h0 = fast_tanh(dv * m.x + bias[0]);
    float h1 = fast_tanh(dv * m.y + bias[1]);
    float4 o;
    o.x = h0 * Wc[0] + h1 * Wc[4] + bc[0];
    o.y = h0 * Wc[1] + h1 * Wc[5] + bc[1];
    o.z = h0 * Wc[2] + h1 * Wc[6] + bc[2];
    o.w = h0 * Wc[3] + h1 * Wc[7] + bc[3];
    reinterpret_cast<float4*>(out)[node] = o;
    if (write_h)
        reinterpret_cast<float2*>(out + (size_t)4 * n)[node] = make_float2(h0, h1);
}

// ---------------- launch ----------------

extern "C" void kernel_launch(void* const* d_in, const int* in_sizes, int n_in,
                              void* d_out, int out_size) {
    const float* x  = (const float*)d_in[0];
    const int*   ei = (const int*)d_in[1];
    const float* W1 = (const float*)d_in[2];  const float* b1 = (const float*)d_in[3];
    const float* W2 = (const float*)d_in[4];  const float* b2 = (const float*)d_in[5];
    const float* W3 = (const float*)d_in[6];  const float* b3 = (const float*)d_in[7];
    const float* W4 = (const float*)d_in[8];  const float* b4 = (const float*)d_in[9];
    const float* W5 = (const float*)d_in[10]; const float* b5 = (const float*)d_in[11];
    const float* Wc = (const float*)d_in[12]; const float* bc = (const float*)d_in[13];

    int n = in_sizes[0] / 128;
    int e = in_sizes[1] / 2;
    const int* row = ei;
    const int* col = ei + e;

    const int TB = 256;
    int nchunks = (n + 4095) / 4096;

    float* bufA = nullptr; float* bufB = nullptr;
    int *cntp = nullptr, *bsump = nullptr;
    cudaGetSymbolAddress((void**)&bufA, g_bufA);
    cudaGetSymbolAddress((void**)&bufB, g_bufB);
    cudaGetSymbolAddress((void**)&cntp, g_cnt);
    cudaGetSymbolAddress((void**)&bsump, g_bsums);

    static cudaStream_t s2 = nullptr;
    static cudaEvent_t evFork = nullptr, evScan1 = nullptr, evJoin = nullptr;
    if (s2 == nullptr) {
        cudaStreamCreateWithFlags(&s2, cudaStreamNonBlocking);
        cudaEventCreateWithFlags(&evFork,  cudaEventDisableTiming);
        cudaEventCreateWithFlags(&evScan1, cudaEventDisableTiming);
        cudaEventCreateWithFlags(&evJoin,  cudaEventDisableTiming);
    }

    bool vec_ok = ((e & 3) == 0) &&
                  (((size_t)col & 15) == 0) &&
                  (((size_t)row & 15) == 0);

    // fork: gemm1_raw independent of CSR build
    cudaEventRecord(evFork, 0);
    cudaStreamWaitEvent(s2, evFork, 0);
    k_gemm1_raw<<<(n + TB - 1) / TB, TB, 0, s2>>>(x, W1, n);   // -> bufA raw

    // default stream: CSR build
    cudaMemsetAsync(cntp, 0, (size_t)n * 4, 0);
    cudaMemsetAsync(bsump, 0, (size_t)MAXCHUNK * 4, 0);
    if (vec_ok) k_count_v4<<<(e / 4 + TB - 1) / TB, TB>>>(col, e / 4);
    else        k_count   <<<(e + TB - 1) / TB, TB>>>(col, e);
    k_scan1<<<(n + 1023) / 1024, 1024>>>(n);
    cudaEventRecord(evScan1, 0);
    k_scan3<<<nchunks, 1024>>>(n, nchunks);     // offsets + woff + pad entries
    if (vec_ok) k_fill_v4<<<(e / 4 + TB - 1) / TB, TB>>>(row, col, e / 4);
    else        k_fill   <<<(e + TB - 1) / TB, TB>>>(row, col, e);

    // s2: scale after scan1 (overlaps scan3+fill)
    cudaStreamWaitEvent(s2, evScan1, 0);
    k_scale<<<(n + TB - 1) / TB, TB, 0, s2>>>(n);
    cudaEventRecord(evJoin, s2);
    cudaStreamWaitEvent(0, evJoin, 0);

    // <D, V, G, PIN, DOUT, VOUT, POUT>
    k_aggv<24, 4, 8, 32, 12, 4, 16><<<((size_t)n * 8 + TB - 1) / TB, TB>>>(bufA, bufB, b1, W2, n);
    k_aggv<12, 4, 4, 16,  6, 2,  8><<<((size_t)n * 4 + TB - 1) / TB, TB>>>(bufB, bufA, b2, W3, n);
    k_aggv< 6, 2, 4,  8,  4, 4,  4><<<((size_t)n * 4 + TB - 1) / TB, TB>>>(bufA, bufB, b3, W4, n);
    k_aggv< 4, 4, 1,  4,  2, 2,  2><<<((size_t)n     + TB - 1) / TB, TB>>>(bufB, bufA, b4, W5, n);

    int write_h = (out_size >= 6 * n) ? 1 : 0;
    k_agg_fin<<<(n + TB - 1) / TB, TB>>>(bufA, b5, Wc, bc, (float*)d_out, n, write_h);
}